// round 14
// baseline (speedup 1.0000x reference)
#include <cuda_runtime.h>
#include <cuda_fp16.h>
#include <math.h>
#include <stdint.h>

// ============================================================================
// Problem dims
// ============================================================================
#define B_ 64
#define T_ 128
#define S_ 1024
#define I_ 1024
#define O_ 1024
#define M_ (B_*T_)   // 8192
#define C_ (I_+O_)   // 2048

// ============================================================================
// Scratch (__device__ globals). fp16 2-way splits (h|l slabs).
// ============================================================================
__device__ __half g_wa2[I_ * 2 * O_];                    // [1024, 2048]
__device__ __half g_qp2[M_ * 2 * I_];                    // [8192, 2048]
__device__ __half g_enc2[(size_t)B_ * S_ * 2 * I_];      // [64][1024, 2048]
__device__ __half g_encT2[(size_t)B_ * I_ * 2 * S_];     // [64][1024, 2048] transposed
__device__ __half g_w2[M_ * 2 * S_];                     // [8192, 2048]
__device__ __half g_cat2[(size_t)M_ * 2 * C_];           // [8192, 4096] row=[ctx_h|dec_h|ctx_l|dec_l]
__device__ __half g_wo2[O_ * 2 * C_];                    // [1024, 4096]

// ============================================================================
// Helpers
// ============================================================================
__device__ __forceinline__ uint32_t smem_u32(const void* p) {
    uint32_t a;
    asm("{ .reg .u64 t; cvta.to.shared.u64 t, %1; cvt.u32.u64 %0, t; }" : "=r"(a) : "l"(p));
    return a;
}

__device__ __forceinline__ void ldsm4(uint32_t r[4], uint32_t addr) {
    asm volatile("ldmatrix.sync.aligned.m8n8.x4.shared.b16 {%0,%1,%2,%3}, [%4];"
        : "=r"(r[0]), "=r"(r[1]), "=r"(r[2]), "=r"(r[3]) : "r"(addr));
}

__device__ __forceinline__ void mma_fp16(float d[4], const uint32_t a[4], const uint32_t b[2]) {
    asm volatile(
        "mma.sync.aligned.m16n8k16.row.col.f32.f16.f16.f32 "
        "{%0,%1,%2,%3}, {%4,%5,%6,%7}, {%8,%9}, {%0,%1,%2,%3};"
        : "+f"(d[0]), "+f"(d[1]), "+f"(d[2]), "+f"(d[3])
        : "r"(a[0]), "r"(a[1]), "r"(a[2]), "r"(a[3]), "r"(b[0]), "r"(b[1]));
}

__device__ __forceinline__ void split2h(float x, __half& h, __half& l) {
    h = __float2half_rn(x);
    l = __float2half_rn(x - __half2float(h));
}

#define CP_ASYNC16(dst, src) \
    asm volatile("cp.async.cg.shared.global [%0], [%1], 16;" :: "r"(dst), "l"(src))
#define CP_COMMIT() asm volatile("cp.async.commit_group;" ::: "memory")
#define CP_WAIT1()  asm volatile("cp.async.wait_group 1;" ::: "memory")
#define CP_WAIT0()  asm volatile("cp.async.wait_group 0;" ::: "memory")

// ============================================================================
// HMMA GEMM, fp16 split with configurable passes, NT, K-major.
// A[rows, pitchA] slabs at s*slabA; B[rows, pitchB] slabs at s*slabB.
// NA/NB = number of A/B slabs loaded. NPASS slab-pair passes:
//   NPASS=3: (0,0),(0,1),(1,0)   full 2-way split product
//   NPASS=2: (0,0),(0,1)         hh + h*l (drop l*h)
//   NPASS=1: (0,0)               hh only
// CTA tile 128x128, BK=64, 2-stage cp.async, 256 threads (8 warps 2x4),
// warp tile 64x32, SW128 swizzle. (R7-proven structure.)
// EPI: 0 = fp32 store, 1 = tanh(acc+bias) fp32, 2 = split2h half store
// ============================================================================
#define TILEB 16384                     // 128x64 half tile bytes

template<int NA, int NB, int NPASS, int EPI>
__global__ void __launch_bounds__(256) tgemm(
    const __half* __restrict__ A, const __half* __restrict__ B,
    float* __restrict__ Cf, __half* __restrict__ Cs,
    const float* __restrict__ bias,
    int K, int pitchA, int pitchB, int slabA, int slabB,
    long long sA, long long sB, long long sC,
    int ldc, int splitOff)
{
    constexpr int STAGEB = (NA + NB) * TILEB;
    extern __shared__ char smem[];
    const uint32_t sb = smem_u32(smem);
    const int tid = threadIdx.x;
    const int lane = tid & 31, wid = tid >> 5;
    const int wm = wid & 1, wn = wid >> 1;         // warp tile (wm*64, wn*32)
    const int n0 = blockIdx.x * 128, m0 = blockIdx.y * 128;
    const long long z = blockIdx.z;

    const __half* Ab = A + z * sA;
    const __half* Bb = B + z * sB;

    const int nchunk = K >> 6;

    float acc[4][4][4];
    #pragma unroll
    for (int i = 0; i < 4; i++)
        #pragma unroll
        for (int j = 0; j < 4; j++)
            #pragma unroll
            for (int q = 0; q < 4; q++) acc[i][j][q] = 0.f;

    // ldmatrix lane-address components
    const int g = lane >> 3, lr = lane & 7;
    const int a_r  = lr + (g & 1) * 8;
    const int a_kb = (g >> 1) * 16;
    const int b_r  = lr + (g >> 1) * 8;
    const int b_kb = (g & 1) * 16;

    auto prefetch = [&](int c, int stage) {
        const int k0 = c << 6;
        const uint32_t sbase = sb + stage * STAGEB;
        #pragma unroll
        for (int s = 0; s < NA; s++) {
            #pragma unroll
            for (int j = 0; j < 4; j++) {       // A slab: 128x64
                int v = tid + 256 * j;
                int r = v >> 3, cc = (v & 7) << 3;
                uint32_t off = (uint32_t)(r * 128 + cc * 2);
                off ^= (off >> 3) & 0x70u;
                CP_ASYNC16(sbase + s * TILEB + off,
                           Ab + (long long)(m0 + r) * pitchA + s * slabA + k0 + cc);
            }
        }
        #pragma unroll
        for (int s = 0; s < NB; s++) {
            #pragma unroll
            for (int j = 0; j < 4; j++) {       // B slab: 128x64
                int v = tid + 256 * j;
                int r = v >> 3, cc = (v & 7) << 3;
                uint32_t off = (uint32_t)(r * 128 + cc * 2);
                off ^= (off >> 3) & 0x70u;
                CP_ASYNC16(sbase + (NA + s) * TILEB + off,
                           Bb + (long long)(n0 + r) * pitchB + s * slabB + k0 + cc);
            }
        }
    };

    prefetch(0, 0);
    CP_COMMIT();

    for (int c = 0; c < nchunk; c++) {
        const int stage = c & 1;
        if (c + 1 < nchunk) {
            prefetch(c + 1, stage ^ 1);
            CP_COMMIT();
            CP_WAIT1();
        } else {
            CP_WAIT0();
        }
        __syncthreads();

        const uint32_t sbase = sb + stage * STAGEB;
        #pragma unroll
        for (int p = 0; p < NPASS; p++) {
            const int pa = (p == 2) ? 1 : 0;    // (0,0),(0,1),(1,0)
            const int pb = (p == 1) ? 1 : 0;
            const uint32_t aBase = sbase + pa * TILEB;
            const uint32_t bBase = sbase + (NA + pb) * TILEB;
            #pragma unroll
            for (int kt = 0; kt < 4; kt++) {
                uint32_t afr[4][4], bfr[2][4];
                #pragma unroll
                for (int mt = 0; mt < 4; mt++) {
                    uint32_t off = (uint32_t)((wm * 64 + mt * 16 + a_r) * 128 + kt * 32 + a_kb);
                    off ^= (off >> 3) & 0x70u;
                    ldsm4(afr[mt], aBase + off);
                }
                #pragma unroll
                for (int ntp = 0; ntp < 2; ntp++) {
                    uint32_t off = (uint32_t)((wn * 32 + ntp * 16 + b_r) * 128 + kt * 32 + b_kb);
                    off ^= (off >> 3) & 0x70u;
                    ldsm4(bfr[ntp], bBase + off);
                }
                #pragma unroll
                for (int mt = 0; mt < 4; mt++)
                    #pragma unroll
                    for (int nt = 0; nt < 4; nt++)
                        mma_fp16(acc[mt][nt], afr[mt], &bfr[nt >> 1][(nt & 1) * 2]);
            }
        }
        __syncthreads();
    }

    // ---- epilogue ----
    const int qr = lane >> 2;
    const int qc = (lane & 3) * 2;
    #pragma unroll
    for (int mt = 0; mt < 4; mt++) {
        #pragma unroll
        for (int nt = 0; nt < 4; nt++) {
            const long long row0 = m0 + wm * 64 + mt * 16 + qr;
            const long long row1 = row0 + 8;
            const int col = n0 + wn * 32 + nt * 8 + qc;
            float v00 = acc[mt][nt][0], v01 = acc[mt][nt][1];
            float v10 = acc[mt][nt][2], v11 = acc[mt][nt][3];
            if (EPI == 0) {
                *reinterpret_cast<float2*>(Cf + z * sC + row0 * ldc + col) = make_float2(v00, v01);
                *reinterpret_cast<float2*>(Cf + z * sC + row1 * ldc + col) = make_float2(v10, v11);
            } else if (EPI == 1) {
                float b0 = bias[col], b1 = bias[col + 1];
                *reinterpret_cast<float2*>(Cf + z * sC + row0 * ldc + col) =
                    make_float2(tanhf(v00 + b0), tanhf(v01 + b1));
                *reinterpret_cast<float2*>(Cf + z * sC + row1 * ldc + col) =
                    make_float2(tanhf(v10 + b0), tanhf(v11 + b1));
            } else {
                __half h0, l0, h1, l1;
                split2h(v00, h0, l0); split2h(v01, h1, l1);
                *reinterpret_cast<__half2*>(Cs + z * sC + row0 * ldc + col) = __halves2half2(h0, h1);
                *reinterpret_cast<__half2*>(Cs + z * sC + row0 * ldc + splitOff + col) = __halves2half2(l0, l1);
                split2h(v10, h0, l0); split2h(v11, h1, l1);
                *reinterpret_cast<__half2*>(Cs + z * sC + row1 * ldc + col) = __halves2half2(h0, h1);
                *reinterpret_cast<__half2*>(Cs + z * sC + row1 * ldc + splitOff + col) = __halves2half2(l0, l1);
            }
        }
    }
}

// ============================================================================
// Conversion kernels (fp16 2-way)
// ============================================================================
__global__ void __launch_bounds__(256) split2_kernel(
    const float* __restrict__ src, __half* __restrict__ dst, int K)
{
    long long i = (long long)blockIdx.x * blockDim.x + threadIdx.x;
    long long rr = i / K;
    int k = (int)(i - rr * K);
    __half h, l;
    split2h(src[i], h, l);
    __half* row = dst + rr * (2LL * K);
    row[k] = h; row[K + k] = l;
}

// dec -> cat2 [8192,4096]: row = [ctx_h(0:1024)|dec_h(1024:2048)|ctx_l(2048:3072)|dec_l(3072:4096)]
__global__ void __launch_bounds__(256) dec_to_cat_kernel(
    const float* __restrict__ dec, __half* __restrict__ cat)
{
    long long i = (long long)blockIdx.x * blockDim.x + threadIdx.x;  // 8192*1024
    long long m = i >> 10;
    int o = (int)(i & 1023);
    __half h, l;
    split2h(dec[i], h, l);
    cat[m * 4096 + 1024 + o] = h;
    cat[m * 4096 + 3072 + o] = l;
}

// enc -> enc2 [b][s, 2048] and encT2 [b][i, 2048] (transposed), h|l
__global__ void __launch_bounds__(1024) enc_split_kernel(
    const float* __restrict__ enc, __half* __restrict__ e2, __half* __restrict__ eT2)
{
    __shared__ __half sh[32][33], sl[32][33];
    int b = blockIdx.z;
    int i0 = blockIdx.x * 32, s0 = blockIdx.y * 32;
    int tx = threadIdx.x, ty = threadIdx.y;
    const float* eb = enc + (size_t)b * S_ * I_;
    float x = eb[(size_t)(s0 + ty) * I_ + i0 + tx];
    __half h, l;
    split2h(x, h, l);
    __half* e2b = e2 + (size_t)b * S_ * 2 * I_;
    e2b[(size_t)(s0 + ty) * 2048 + i0 + tx] = h;
    e2b[(size_t)(s0 + ty) * 2048 + 1024 + i0 + tx] = l;
    sh[ty][tx] = h; sl[ty][tx] = l;
    __syncthreads();
    __half* eTb = eT2 + (size_t)b * I_ * 2 * S_;
    eTb[(size_t)(i0 + ty) * 2048 + s0 + tx] = sh[tx][ty];
    eTb[(size_t)(i0 + ty) * 2048 + 1024 + s0 + tx] = sl[tx][ty];
}

// ============================================================================
// Masked softmax over rows of [B*T, S=1024], in place (fp32), fused fp16 split.
// ============================================================================
__device__ __forceinline__ float warpMax(float v) {
    #pragma unroll
    for (int o = 16; o; o >>= 1) v = fmaxf(v, __shfl_xor_sync(0xffffffffu, v, o));
    return v;
}
__device__ __forceinline__ float warpSum(float v) {
    #pragma unroll
    for (int o = 16; o; o >>= 1) v += __shfl_xor_sync(0xffffffffu, v, o);
    return v;
}

__global__ void __launch_bounds__(256) softmax_mask(
    float* __restrict__ w, const int* __restrict__ mask, __half* __restrict__ wsplit)
{
    const int S = 1024;
    long long row = blockIdx.x;
    int b = (int)(row >> 7);
    float* sr = w + row * S;
    const int* mr = mask + (long long)b * S;
    int tid = threadIdx.x;

    float4 v = *reinterpret_cast<const float4*>(sr + tid * 4);
    int4 m = *reinterpret_cast<const int4*>(mr + tid * 4);

    bool msk[4] = {m.x != 0, m.y != 0, m.z != 0, m.w != 0};
    float x[4];
    x[0] = msk[0] ? -INFINITY : v.x;
    x[1] = msk[1] ? -INFINITY : v.y;
    x[2] = msk[2] ? -INFINITY : v.z;
    x[3] = msk[3] ? -INFINITY : v.w;

    float mx = fmaxf(fmaxf(x[0], x[1]), fmaxf(x[2], x[3]));

    __shared__ float sh[8];
    float wm = warpMax(mx);
    if ((tid & 31) == 0) sh[tid >> 5] = wm;
    __syncthreads();
    if (tid < 32) {
        float t = (tid < 8) ? sh[tid] : -INFINITY;
        t = warpMax(t);
        if (tid == 0) sh[0] = t;
    }
    __syncthreads();
    mx = sh[0];

    float e[4], s = 0.f;
    #pragma unroll
    for (int j = 0; j < 4; j++) {
        e[j] = msk[j] ? 0.f : __expf(x[j] - mx);
        s += e[j];
    }
    __syncthreads();
    float ws = warpSum(s);
    if ((tid & 31) == 0) sh[tid >> 5] = ws;
    __syncthreads();
    if (tid < 32) {
        float t = (tid < 8) ? sh[tid] : 0.f;
        t = warpSum(t);
        if (tid == 0) sh[0] = t;
    }
    __syncthreads();
    float inv = 1.0f / sh[0];

    float o[4] = {e[0] * inv, e[1] * inv, e[2] * inv, e[3] * inv};
    float4 of = {o[0], o[1], o[2], o[3]};
    *reinterpret_cast<float4*>(sr + tid * 4) = of;

    __half* wrow = wsplit + row * 2048;
    #pragma unroll
    for (int j = 0; j < 4; j++) {
        __half h, l;
        split2h(o[j], h, l);
        wrow[tid * 4 + j] = h;
        wrow[1024 + tid * 4 + j] = l;
    }
}

// ============================================================================
extern "C" void kernel_launch(void* const* d_in, const int* in_sizes, int n_in,
                              void* d_out, int out_size)
{
    const float* dec    = (const float*)d_in[0];   // [64,128,1024]
    const float* enc    = (const float*)d_in[1];   // [64,1024,1024]
    const int*   mask   = (const int*)d_in[2];     // [64,1024] bool->int32
    const float* W_attn = (const float*)d_in[3];   // [1024,1024]
    const float* W_out  = (const float*)d_in[4];   // [1024,2048]
    const float* b_out  = (const float*)d_in[5];   // [1024]

    float* out     = (float*)d_out;                 // attn_outputs [64,128,1024]
    float* weights = out + (long long)M_ * O_;      // attn_weights [64,128,1024]

    __half *wa2, *qp2, *enc2, *encT2, *w2, *cat2, *wo2;
    cudaGetSymbolAddress((void**)&wa2,   g_wa2);
    cudaGetSymbolAddress((void**)&qp2,   g_qp2);
    cudaGetSymbolAddress((void**)&enc2,  g_enc2);
    cudaGetSymbolAddress((void**)&encT2, g_encT2);
    cudaGetSymbolAddress((void**)&w2,    g_w2);
    cudaGetSymbolAddress((void**)&cat2,  g_cat2);
    cudaGetSymbolAddress((void**)&wo2,   g_wo2);

    const int SMB22 = 2 * 4 * TILEB;  // 131072: NA=2,NB=2
    const int SMB11 = 2 * 2 * TILEB;  // 65536:  NA=1,NB=1
    const int SMB12 = 2 * 3 * TILEB;  // 98304:  NA=1,NB=2
    cudaFuncSetAttribute((const void*)tgemm<2,2,3,2>, cudaFuncAttributeMaxDynamicSharedMemorySize, SMB22);
    cudaFuncSetAttribute((const void*)tgemm<2,2,3,0>, cudaFuncAttributeMaxDynamicSharedMemorySize, SMB22);
    cudaFuncSetAttribute((const void*)tgemm<1,1,1,2>, cudaFuncAttributeMaxDynamicSharedMemorySize, SMB11);
    cudaFuncSetAttribute((const void*)tgemm<1,2,2,1>, cudaFuncAttributeMaxDynamicSharedMemorySize, SMB12);

    // --- Conversions ---
    split2_kernel<<<(I_ * (long long)O_) / 256, 256>>>(W_attn, wa2, O_);
    split2_kernel<<<(O_ * (long long)C_) / 256, 256>>>(W_out, wo2, C_);
    enc_split_kernel<<<dim3(I_ / 32, S_ / 32, B_), dim3(32, 32)>>>(enc, enc2, encT2);
    dec_to_cat_kernel<<<(M_ * (long long)O_) / 256, 256>>>(dec, cat2);

    // --- GEMM1: q_proj = dec . W_attn^T  (3 passes; A = dec slabs inside cat2) ---
    tgemm<2,2,3,2><<<dim3(I_ / 128, M_ / 128, 1), 256, SMB22>>>(
        cat2 + 1024, wa2, nullptr, qp2, nullptr,
        O_, /*pitchA*/4096, /*pitchB*/2048, /*slabA*/2048, /*slabB*/1024,
        0, 0, 0, 2 * I_, I_);

    // --- GEMM2: scores[b] = q[b] . enc[b]^T  (3 passes) -> weights fp32 ---
    tgemm<2,2,3,0><<<dim3(S_ / 128, T_ / 128, B_), 256, SMB22>>>(
        qp2, enc2, weights, nullptr, nullptr,
        I_, 2 * I_, 2 * I_, I_, I_,
        (long long)T_ * 2 * I_, (long long)S_ * 2 * I_, (long long)T_ * S_,
        S_, 0);

    // --- Softmax + fused fp16 split -> w2 ---
    softmax_mask<<<M_, 256>>>(weights, mask, w2);

    // --- GEMM4: ctx[b] = w[b] . encT[b]^T  (1 pass hh; errors average out in GEMM5) ---
    tgemm<1,1,1,2><<<dim3(I_ / 128, T_ / 128, B_), 256, SMB11>>>(
        w2, encT2, nullptr, cat2, nullptr,
        S_, 2 * S_, 2 * S_, S_, S_,
        (long long)T_ * 2 * S_, (long long)I_ * 2 * S_, (long long)T_ * 2 * C_,
        2 * C_, C_);

    // --- GEMM5: out = tanh(cat . W_out^T + b)  (2 passes: hh + h*Wl) ---
    tgemm<1,2,2,1><<<dim3(O_ / 128, M_ / 128, 1), 256, SMB12>>>(
        cat2, wo2, out, nullptr, b_out,
        C_, 2 * C_, 2 * C_, C_, C_,
        0, 0, 0, O_, 0);
}

// round 15
// speedup vs baseline: 1.3513x; 1.3513x over previous
#include <cuda_runtime.h>
#include <cuda_fp16.h>
#include <math.h>
#include <stdint.h>

// ============================================================================
// Problem dims
// ============================================================================
#define B_ 64
#define T_ 128
#define S_ 1024
#define I_ 1024
#define O_ 1024
#define M_ (B_*T_)   // 8192
#define C_ (I_+O_)   // 2048

// ============================================================================
// Scratch (__device__ globals). fp16 2-way splits (h|l slabs).
// ============================================================================
__device__ __half g_wa2[I_ * 2 * O_];                    // [1024, 2048]
__device__ __half g_qp2[M_ * 2 * I_];                    // [8192, 2048]
__device__ __half g_enc2[(size_t)B_ * S_ * 2 * I_];      // [64][1024, 2048]
__device__ __half g_encT2[(size_t)B_ * I_ * 2 * S_];     // [64][1024, 2048] transposed
__device__ __half g_w2[M_ * 2 * S_];                     // [8192, 2048]
__device__ __half g_cat2[(size_t)M_ * 2 * C_];           // [8192, 4096] row=[ctx_h|dec_h|ctx_l|dec_l]
__device__ __half g_wo2[O_ * 2 * C_];                    // [1024, 4096]

// ============================================================================
// Helpers
// ============================================================================
__device__ __forceinline__ uint32_t smem_u32(const void* p) {
    uint32_t a;
    asm("{ .reg .u64 t; cvta.to.shared.u64 t, %1; cvt.u32.u64 %0, t; }" : "=r"(a) : "l"(p));
    return a;
}

__device__ __forceinline__ void ldsm4(uint32_t r[4], uint32_t addr) {
    asm volatile("ldmatrix.sync.aligned.m8n8.x4.shared.b16 {%0,%1,%2,%3}, [%4];"
        : "=r"(r[0]), "=r"(r[1]), "=r"(r[2]), "=r"(r[3]) : "r"(addr));
}

__device__ __forceinline__ void mma_fp16(float d[4], const uint32_t a[4], const uint32_t b[2]) {
    asm volatile(
        "mma.sync.aligned.m16n8k16.row.col.f32.f16.f16.f32 "
        "{%0,%1,%2,%3}, {%4,%5,%6,%7}, {%8,%9}, {%0,%1,%2,%3};"
        : "+f"(d[0]), "+f"(d[1]), "+f"(d[2]), "+f"(d[3])
        : "r"(a[0]), "r"(a[1]), "r"(a[2]), "r"(a[3]), "r"(b[0]), "r"(b[1]));
}

__device__ __forceinline__ void split2h(float x, __half& h, __half& l) {
    h = __float2half_rn(x);
    l = __float2half_rn(x - __half2float(h));
}

#define CP_ASYNC16(dst, src) \
    asm volatile("cp.async.cg.shared.global [%0], [%1], 16;" :: "r"(dst), "l"(src))
#define CP_COMMIT() asm volatile("cp.async.commit_group;" ::: "memory")
#define CP_WAIT1()  asm volatile("cp.async.wait_group 1;" ::: "memory")
#define CP_WAIT0()  asm volatile("cp.async.wait_group 0;" ::: "memory")

// ============================================================================
// HMMA GEMM, fp16 2-way split, NT, K-major. R7-identical memory structure:
// ALWAYS loads 2 A-slabs + 2 B-slabs per BK=64 chunk (2-stage cp.async,
// 131KB smem). ONLY the compute pass count varies:
//   NPASS=3: (0,0),(0,1),(1,0)   full split product
//   NPASS=2: (0,0),(0,1)         drop lo*hi correction
// CTA tile 128x128, 256 threads (8 warps 2x4), warp tile 64x32, SW128.
// EPI: 0 = fp32 store, 1 = tanh(acc+bias) fp32, 2 = split2h half store
// ============================================================================
#define TILEB 16384                     // 128x64 half tile bytes
#define STAGEB (4*TILEB)                // 2 A-slabs + 2 B-slabs = 65536

template<int NPASS, int EPI>
__global__ void __launch_bounds__(256) tgemm(
    const __half* __restrict__ A, const __half* __restrict__ B,
    float* __restrict__ Cf, __half* __restrict__ Cs,
    const float* __restrict__ bias,
    int K, int pitchA, int pitchB, int slabA, int slabB,
    long long sA, long long sB, long long sC,
    int ldc, int splitOff)
{
    extern __shared__ char smem[];
    const uint32_t sb = smem_u32(smem);
    const int tid = threadIdx.x;
    const int lane = tid & 31, wid = tid >> 5;
    const int wm = wid & 1, wn = wid >> 1;         // warp tile (wm*64, wn*32)
    const int n0 = blockIdx.x * 128, m0 = blockIdx.y * 128;
    const long long z = blockIdx.z;

    const __half* Ab = A + z * sA;
    const __half* Bb = B + z * sB;

    const int nchunk = K >> 6;

    float acc[4][4][4];
    #pragma unroll
    for (int i = 0; i < 4; i++)
        #pragma unroll
        for (int j = 0; j < 4; j++)
            #pragma unroll
            for (int q = 0; q < 4; q++) acc[i][j][q] = 0.f;

    // ldmatrix lane-address components
    const int g = lane >> 3, lr = lane & 7;
    const int a_r  = lr + (g & 1) * 8;
    const int a_kb = (g >> 1) * 16;
    const int b_r  = lr + (g >> 1) * 8;
    const int b_kb = (g & 1) * 16;

    auto prefetch = [&](int c, int stage) {
        const int k0 = c << 6;
        const uint32_t sbase = sb + stage * STAGEB;
        #pragma unroll
        for (int s = 0; s < 2; s++) {
            #pragma unroll
            for (int j = 0; j < 4; j++) {       // A slab: 128x64
                int v = tid + 256 * j;
                int r = v >> 3, cc = (v & 7) << 3;
                uint32_t off = (uint32_t)(r * 128 + cc * 2);
                off ^= (off >> 3) & 0x70u;
                CP_ASYNC16(sbase + s * TILEB + off,
                           Ab + (long long)(m0 + r) * pitchA + s * slabA + k0 + cc);
            }
            #pragma unroll
            for (int j = 0; j < 4; j++) {       // B slab: 128x64
                int v = tid + 256 * j;
                int r = v >> 3, cc = (v & 7) << 3;
                uint32_t off = (uint32_t)(r * 128 + cc * 2);
                off ^= (off >> 3) & 0x70u;
                CP_ASYNC16(sbase + (2 + s) * TILEB + off,
                           Bb + (long long)(n0 + r) * pitchB + s * slabB + k0 + cc);
            }
        }
    };

    prefetch(0, 0);
    CP_COMMIT();

    for (int c = 0; c < nchunk; c++) {
        const int stage = c & 1;
        if (c + 1 < nchunk) {
            prefetch(c + 1, stage ^ 1);
            CP_COMMIT();
            CP_WAIT1();
        } else {
            CP_WAIT0();
        }
        __syncthreads();

        const uint32_t sbase = sb + stage * STAGEB;
        #pragma unroll
        for (int p = 0; p < NPASS; p++) {
            const int pa = (p == 2) ? 1 : 0;    // (0,0),(0,1),(1,0)
            const int pb = (p == 1) ? 1 : 0;
            const uint32_t aBase = sbase + pa * TILEB;
            const uint32_t bBase = sbase + (2 + pb) * TILEB;
            #pragma unroll
            for (int kt = 0; kt < 4; kt++) {
                uint32_t afr[4][4], bfr[2][4];
                #pragma unroll
                for (int mt = 0; mt < 4; mt++) {
                    uint32_t off = (uint32_t)((wm * 64 + mt * 16 + a_r) * 128 + kt * 32 + a_kb);
                    off ^= (off >> 3) & 0x70u;
                    ldsm4(afr[mt], aBase + off);
                }
                #pragma unroll
                for (int ntp = 0; ntp < 2; ntp++) {
                    uint32_t off = (uint32_t)((wn * 32 + ntp * 16 + b_r) * 128 + kt * 32 + b_kb);
                    off ^= (off >> 3) & 0x70u;
                    ldsm4(bfr[ntp], bBase + off);
                }
                #pragma unroll
                for (int mt = 0; mt < 4; mt++)
                    #pragma unroll
                    for (int nt = 0; nt < 4; nt++)
                        mma_fp16(acc[mt][nt], afr[mt], &bfr[nt >> 1][(nt & 1) * 2]);
            }
        }
        __syncthreads();
    }

    // ---- epilogue ----
    const int qr = lane >> 2;
    const int qc = (lane & 3) * 2;
    #pragma unroll
    for (int mt = 0; mt < 4; mt++) {
        #pragma unroll
        for (int nt = 0; nt < 4; nt++) {
            const long long row0 = m0 + wm * 64 + mt * 16 + qr;
            const long long row1 = row0 + 8;
            const int col = n0 + wn * 32 + nt * 8 + qc;
            float v00 = acc[mt][nt][0], v01 = acc[mt][nt][1];
            float v10 = acc[mt][nt][2], v11 = acc[mt][nt][3];
            if (EPI == 0) {
                *reinterpret_cast<float2*>(Cf + z * sC + row0 * ldc + col) = make_float2(v00, v01);
                *reinterpret_cast<float2*>(Cf + z * sC + row1 * ldc + col) = make_float2(v10, v11);
            } else if (EPI == 1) {
                float b0 = bias[col], b1 = bias[col + 1];
                *reinterpret_cast<float2*>(Cf + z * sC + row0 * ldc + col) =
                    make_float2(tanhf(v00 + b0), tanhf(v01 + b1));
                *reinterpret_cast<float2*>(Cf + z * sC + row1 * ldc + col) =
                    make_float2(tanhf(v10 + b0), tanhf(v11 + b1));
            } else {
                __half h0, l0, h1, l1;
                split2h(v00, h0, l0); split2h(v01, h1, l1);
                *reinterpret_cast<__half2*>(Cs + z * sC + row0 * ldc + col) = __halves2half2(h0, h1);
                *reinterpret_cast<__half2*>(Cs + z * sC + row0 * ldc + splitOff + col) = __halves2half2(l0, l1);
                split2h(v10, h0, l0); split2h(v11, h1, l1);
                *reinterpret_cast<__half2*>(Cs + z * sC + row1 * ldc + col) = __halves2half2(h0, h1);
                *reinterpret_cast<__half2*>(Cs + z * sC + row1 * ldc + splitOff + col) = __halves2half2(l0, l1);
            }
        }
    }
}

// ============================================================================
// Conversion kernels (fp16 2-way)
// ============================================================================
__global__ void __launch_bounds__(256) split2_kernel(
    const float* __restrict__ src, __half* __restrict__ dst, int K)
{
    long long i = (long long)blockIdx.x * blockDim.x + threadIdx.x;
    long long rr = i / K;
    int k = (int)(i - rr * K);
    __half h, l;
    split2h(src[i], h, l);
    __half* row = dst + rr * (2LL * K);
    row[k] = h; row[K + k] = l;
}

// dec -> cat2 [8192,4096]: row = [ctx_h(0:1024)|dec_h(1024:2048)|ctx_l(2048:3072)|dec_l(3072:4096)]
__global__ void __launch_bounds__(256) dec_to_cat_kernel(
    const float* __restrict__ dec, __half* __restrict__ cat)
{
    long long i = (long long)blockIdx.x * blockDim.x + threadIdx.x;  // 8192*1024
    long long m = i >> 10;
    int o = (int)(i & 1023);
    __half h, l;
    split2h(dec[i], h, l);
    cat[m * 4096 + 1024 + o] = h;
    cat[m * 4096 + 3072 + o] = l;
}

// enc -> enc2 [b][s, 2048] and encT2 [b][i, 2048] (transposed), h|l
__global__ void __launch_bounds__(1024) enc_split_kernel(
    const float* __restrict__ enc, __half* __restrict__ e2, __half* __restrict__ eT2)
{
    __shared__ __half sh[32][33], sl[32][33];
    int b = blockIdx.z;
    int i0 = blockIdx.x * 32, s0 = blockIdx.y * 32;
    int tx = threadIdx.x, ty = threadIdx.y;
    const float* eb = enc + (size_t)b * S_ * I_;
    float x = eb[(size_t)(s0 + ty) * I_ + i0 + tx];
    __half h, l;
    split2h(x, h, l);
    __half* e2b = e2 + (size_t)b * S_ * 2 * I_;
    e2b[(size_t)(s0 + ty) * 2048 + i0 + tx] = h;
    e2b[(size_t)(s0 + ty) * 2048 + 1024 + i0 + tx] = l;
    sh[ty][tx] = h; sl[ty][tx] = l;
    __syncthreads();
    __half* eTb = eT2 + (size_t)b * I_ * 2 * S_;
    eTb[(size_t)(i0 + ty) * 2048 + s0 + tx] = sh[tx][ty];
    eTb[(size_t)(i0 + ty) * 2048 + 1024 + s0 + tx] = sl[tx][ty];
}

// ============================================================================
// Masked softmax over rows of [B*T, S=1024], in place (fp32), fused fp16 split.
// ============================================================================
__device__ __forceinline__ float warpMax(float v) {
    #pragma unroll
    for (int o = 16; o; o >>= 1) v = fmaxf(v, __shfl_xor_sync(0xffffffffu, v, o));
    return v;
}
__device__ __forceinline__ float warpSum(float v) {
    #pragma unroll
    for (int o = 16; o; o >>= 1) v += __shfl_xor_sync(0xffffffffu, v, o);
    return v;
}

__global__ void __launch_bounds__(256) softmax_mask(
    float* __restrict__ w, const int* __restrict__ mask, __half* __restrict__ wsplit)
{
    const int S = 1024;
    long long row = blockIdx.x;
    int b = (int)(row >> 7);
    float* sr = w + row * S;
    const int* mr = mask + (long long)b * S;
    int tid = threadIdx.x;

    float4 v = *reinterpret_cast<const float4*>(sr + tid * 4);
    int4 m = *reinterpret_cast<const int4*>(mr + tid * 4);

    bool msk[4] = {m.x != 0, m.y != 0, m.z != 0, m.w != 0};
    float x[4];
    x[0] = msk[0] ? -INFINITY : v.x;
    x[1] = msk[1] ? -INFINITY : v.y;
    x[2] = msk[2] ? -INFINITY : v.z;
    x[3] = msk[3] ? -INFINITY : v.w;

    float mx = fmaxf(fmaxf(x[0], x[1]), fmaxf(x[2], x[3]));

    __shared__ float sh[8];
    float wm = warpMax(mx);
    if ((tid & 31) == 0) sh[tid >> 5] = wm;
    __syncthreads();
    if (tid < 32) {
        float t = (tid < 8) ? sh[tid] : -INFINITY;
        t = warpMax(t);
        if (tid == 0) sh[0] = t;
    }
    __syncthreads();
    mx = sh[0];

    float e[4], s = 0.f;
    #pragma unroll
    for (int j = 0; j < 4; j++) {
        e[j] = msk[j] ? 0.f : __expf(x[j] - mx);
        s += e[j];
    }
    __syncthreads();
    float ws = warpSum(s);
    if ((tid & 31) == 0) sh[tid >> 5] = ws;
    __syncthreads();
    if (tid < 32) {
        float t = (tid < 8) ? sh[tid] : 0.f;
        t = warpSum(t);
        if (tid == 0) sh[0] = t;
    }
    __syncthreads();
    float inv = 1.0f / sh[0];

    float o[4] = {e[0] * inv, e[1] * inv, e[2] * inv, e[3] * inv};
    float4 of = {o[0], o[1], o[2], o[3]};
    *reinterpret_cast<float4*>(sr + tid * 4) = of;

    __half* wrow = wsplit + row * 2048;
    #pragma unroll
    for (int j = 0; j < 4; j++) {
        __half h, l;
        split2h(o[j], h, l);
        wrow[tid * 4 + j] = h;
        wrow[1024 + tid * 4 + j] = l;
    }
}

// ============================================================================
extern "C" void kernel_launch(void* const* d_in, const int* in_sizes, int n_in,
                              void* d_out, int out_size)
{
    const float* dec    = (const float*)d_in[0];   // [64,128,1024]
    const float* enc    = (const float*)d_in[1];   // [64,1024,1024]
    const int*   mask   = (const int*)d_in[2];     // [64,1024] bool->int32
    const float* W_attn = (const float*)d_in[3];   // [1024,1024]
    const float* W_out  = (const float*)d_in[4];   // [1024,2048]
    const float* b_out  = (const float*)d_in[5];   // [1024]

    float* out     = (float*)d_out;                 // attn_outputs [64,128,1024]
    float* weights = out + (long long)M_ * O_;      // attn_weights [64,128,1024]

    __half *wa2, *qp2, *enc2, *encT2, *w2, *cat2, *wo2;
    cudaGetSymbolAddress((void**)&wa2,   g_wa2);
    cudaGetSymbolAddress((void**)&qp2,   g_qp2);
    cudaGetSymbolAddress((void**)&enc2,  g_enc2);
    cudaGetSymbolAddress((void**)&encT2, g_encT2);
    cudaGetSymbolAddress((void**)&w2,    g_w2);
    cudaGetSymbolAddress((void**)&cat2,  g_cat2);
    cudaGetSymbolAddress((void**)&wo2,   g_wo2);

    const int SMB = 2 * STAGEB;  // 131072 — identical to the R7 champion
    cudaFuncSetAttribute((const void*)tgemm<3,2>, cudaFuncAttributeMaxDynamicSharedMemorySize, SMB);
    cudaFuncSetAttribute((const void*)tgemm<3,0>, cudaFuncAttributeMaxDynamicSharedMemorySize, SMB);
    cudaFuncSetAttribute((const void*)tgemm<2,2>, cudaFuncAttributeMaxDynamicSharedMemorySize, SMB);
    cudaFuncSetAttribute((const void*)tgemm<2,1>, cudaFuncAttributeMaxDynamicSharedMemorySize, SMB);

    // --- Conversions ---
    split2_kernel<<<(I_ * (long long)O_) / 256, 256>>>(W_attn, wa2, O_);
    split2_kernel<<<(O_ * (long long)C_) / 256, 256>>>(W_out, wo2, C_);
    enc_split_kernel<<<dim3(I_ / 32, S_ / 32, B_), dim3(32, 32)>>>(enc, enc2, encT2);
    dec_to_cat_kernel<<<(M_ * (long long)O_) / 256, 256>>>(dec, cat2);

    // --- GEMM1: q_proj = dec . W_attn^T  (3 passes; A = dec slabs inside cat2) ---
    tgemm<3,2><<<dim3(I_ / 128, M_ / 128, 1), 256, SMB>>>(
        cat2 + 1024, wa2, nullptr, qp2, nullptr,
        O_, /*pitchA*/4096, /*pitchB*/2048, /*slabA*/2048, /*slabB*/1024,
        0, 0, 0, 2 * I_, I_);

    // --- GEMM2: scores[b] = q[b] . enc[b]^T  (3 passes) -> weights fp32 ---
    tgemm<3,0><<<dim3(S_ / 128, T_ / 128, B_), 256, SMB>>>(
        qp2, enc2, weights, nullptr, nullptr,
        I_, 2 * I_, 2 * I_, I_, I_,
        (long long)T_ * 2 * I_, (long long)S_ * 2 * I_, (long long)T_ * S_,
        S_, 0);

    // --- Softmax + fused fp16 split -> w2 ---
    softmax_mask<<<M_, 256>>>(weights, mask, w2);

    // --- GEMM4: ctx[b] = w[b] . encT[b]^T  (2 passes: hh + w_h*e_l) ---
    tgemm<2,2><<<dim3(I_ / 128, T_ / 128, B_), 256, SMB>>>(
        w2, encT2, nullptr, cat2, nullptr,
        S_, 2 * S_, 2 * S_, S_, S_,
        (long long)T_ * 2 * S_, (long long)I_ * 2 * S_, (long long)T_ * 2 * C_,
        2 * C_, C_);

    // --- GEMM5: out = tanh(cat . W_out^T + b)  (2 passes: hh + cat_h*W_l) ---
    tgemm<2,1><<<dim3(O_ / 128, M_ / 128, 1), 256, SMB>>>(
        cat2, wo2, out, nullptr, b_out,
        C_, 2 * C_, 2 * C_, C_, C_,
        0, 0, 0, O_, 0);
}

// round 16
// speedup vs baseline: 1.4813x; 1.0962x over previous
#include <cuda_runtime.h>
#include <cuda_fp16.h>
#include <math.h>
#include <stdint.h>

// ============================================================================
// Problem dims
// ============================================================================
#define B_ 64
#define T_ 128
#define S_ 1024
#define I_ 1024
#define O_ 1024
#define M_ (B_*T_)   // 8192
#define C_ (I_+O_)   // 2048

// ============================================================================
// Scratch (__device__ globals). fp16 2-way splits (h|l slabs).
// ============================================================================
__device__ __half g_wa2[I_ * 2 * O_];                    // [1024, 2048]
__device__ __half g_qp2[M_ * 2 * I_];                    // [8192, 2048]
__device__ __half g_enc2[(size_t)B_ * S_ * 2 * I_];      // [64][1024, 2048]
__device__ __half g_encT2[(size_t)B_ * I_ * 2 * S_];     // [64][1024, 2048] transposed
__device__ __half g_w2[M_ * 2 * S_];                     // [8192, 2048] (only hi slab written/used)
__device__ __half g_cat2[(size_t)M_ * 2 * C_];           // [8192, 4096] row=[ctx_h|dec_h|ctx_l|dec_l]
__device__ __half g_wo2[O_ * 2 * C_];                    // [1024, 4096]

// ============================================================================
// Helpers
// ============================================================================
__device__ __forceinline__ uint32_t smem_u32(const void* p) {
    uint32_t a;
    asm("{ .reg .u64 t; cvta.to.shared.u64 t, %1; cvt.u32.u64 %0, t; }" : "=r"(a) : "l"(p));
    return a;
}

__device__ __forceinline__ void ldsm4(uint32_t r[4], uint32_t addr) {
    asm volatile("ldmatrix.sync.aligned.m8n8.x4.shared.b16 {%0,%1,%2,%3}, [%4];"
        : "=r"(r[0]), "=r"(r[1]), "=r"(r[2]), "=r"(r[3]) : "r"(addr));
}

__device__ __forceinline__ void mma_fp16(float d[4], const uint32_t a[4], const uint32_t b[2]) {
    asm volatile(
        "mma.sync.aligned.m16n8k16.row.col.f32.f16.f16.f32 "
        "{%0,%1,%2,%3}, {%4,%5,%6,%7}, {%8,%9}, {%0,%1,%2,%3};"
        : "+f"(d[0]), "+f"(d[1]), "+f"(d[2]), "+f"(d[3])
        : "r"(a[0]), "r"(a[1]), "r"(a[2]), "r"(a[3]), "r"(b[0]), "r"(b[1]));
}

__device__ __forceinline__ void split2h(float x, __half& h, __half& l) {
    h = __float2half_rn(x);
    l = __float2half_rn(x - __half2float(h));
}

#define CP_ASYNC16(dst, src) \
    asm volatile("cp.async.cg.shared.global [%0], [%1], 16;" :: "r"(dst), "l"(src))
#define CP_COMMIT() asm volatile("cp.async.commit_group;" ::: "memory")
#define CP_WAIT1()  asm volatile("cp.async.wait_group 1;" ::: "memory")
#define CP_WAIT0()  asm volatile("cp.async.wait_group 0;" ::: "memory")

// ============================================================================
// HMMA GEMM, fp16 2-way split, NT, K-major. R11-identical pipeline skeleton
// (BK=64, 2-stage cp.async, 131KB smem, 256 threads 8 warps 2x4, SW128).
// NAL = A slabs actually FETCHED (smem layout always reserves 2 -> occupancy
// identical regardless). NPASS compute passes with fragment reuse:
//   order: A0xB0, A0xB1 (B1 fresh), A1xB0 (B0 kept in regs)
//   NPASS=3: all three   NPASS=2: first two (A slab1 unused -> NAL=1)
// EPI: 0 = fp32, 1 = tanh(acc+bias) fp32, 2 = split2h hi+lo, 3 = hi-only half
// ============================================================================
#define TILEB 16384                     // 128x64 half tile bytes
#define STAGEB (4*TILEB)                // layout: [A0][A1][B0][B1] = 65536

template<int NAL, int NPASS, int EPI>
__global__ void __launch_bounds__(256) tgemm(
    const __half* __restrict__ A, const __half* __restrict__ B,
    float* __restrict__ Cf, __half* __restrict__ Cs,
    const float* __restrict__ bias,
    int K, int pitchA, int pitchB, int slabA, int slabB,
    long long sA, long long sB, long long sC,
    int ldc, int splitOff)
{
    extern __shared__ char smem[];
    const uint32_t sb = smem_u32(smem);
    const int tid = threadIdx.x;
    const int lane = tid & 31, wid = tid >> 5;
    const int wm = wid & 1, wn = wid >> 1;         // warp tile (wm*64, wn*32)
    const int n0 = blockIdx.x * 128, m0 = blockIdx.y * 128;
    const long long z = blockIdx.z;

    const __half* Ab = A + z * sA;
    const __half* Bb = B + z * sB;

    const int nchunk = K >> 6;

    float acc[4][4][4];
    #pragma unroll
    for (int i = 0; i < 4; i++)
        #pragma unroll
        for (int j = 0; j < 4; j++)
            #pragma unroll
            for (int q = 0; q < 4; q++) acc[i][j][q] = 0.f;

    // ldmatrix lane-address components
    const int g = lane >> 3, lr = lane & 7;
    const int a_r  = lr + (g & 1) * 8;
    const int a_kb = (g >> 1) * 16;
    const int b_r  = lr + (g >> 1) * 8;
    const int b_kb = (g & 1) * 16;

    auto prefetch = [&](int c, int stage) {
        const int k0 = c << 6;
        const uint32_t sbase = sb + stage * STAGEB;
        #pragma unroll
        for (int s = 0; s < NAL; s++) {
            #pragma unroll
            for (int j = 0; j < 4; j++) {       // A slab: 128x64
                int v = tid + 256 * j;
                int r = v >> 3, cc = (v & 7) << 3;
                uint32_t off = (uint32_t)(r * 128 + cc * 2);
                off ^= (off >> 3) & 0x70u;
                CP_ASYNC16(sbase + s * TILEB + off,
                           Ab + (long long)(m0 + r) * pitchA + s * slabA + k0 + cc);
            }
        }
        #pragma unroll
        for (int s = 0; s < 2; s++) {
            #pragma unroll
            for (int j = 0; j < 4; j++) {       // B slab: 128x64
                int v = tid + 256 * j;
                int r = v >> 3, cc = (v & 7) << 3;
                uint32_t off = (uint32_t)(r * 128 + cc * 2);
                off ^= (off >> 3) & 0x70u;
                CP_ASYNC16(sbase + (2 + s) * TILEB + off,
                           Bb + (long long)(n0 + r) * pitchB + s * slabB + k0 + cc);
            }
        }
    };

    prefetch(0, 0);
    CP_COMMIT();

    for (int c = 0; c < nchunk; c++) {
        const int stage = c & 1;
        if (c + 1 < nchunk) {
            prefetch(c + 1, stage ^ 1);
            CP_COMMIT();
            CP_WAIT1();
        } else {
            CP_WAIT0();
        }
        __syncthreads();

        const uint32_t sbase = sb + stage * STAGEB;
        #pragma unroll
        for (int kt = 0; kt < 4; kt++) {
            uint32_t a0[4][4], b0[2][4];
            // A slab 0 fragments (reused across B passes)
            #pragma unroll
            for (int mt = 0; mt < 4; mt++) {
                uint32_t off = (uint32_t)((wm * 64 + mt * 16 + a_r) * 128 + kt * 32 + a_kb);
                off ^= (off >> 3) & 0x70u;
                ldsm4(a0[mt], sbase + 0 * TILEB + off);
            }
            // B slab 0 fragments (kept for the A1 pass)
            #pragma unroll
            for (int ntp = 0; ntp < 2; ntp++) {
                uint32_t off = (uint32_t)((wn * 32 + ntp * 16 + b_r) * 128 + kt * 32 + b_kb);
                off ^= (off >> 3) & 0x70u;
                ldsm4(b0[ntp], sbase + 2 * TILEB + off);
            }
            #pragma unroll
            for (int mt = 0; mt < 4; mt++)
                #pragma unroll
                for (int nt = 0; nt < 4; nt++)
                    mma_fp16(acc[mt][nt], a0[mt], &b0[nt >> 1][(nt & 1) * 2]);

            if (NPASS >= 2) {
                uint32_t b1[2][4];
                #pragma unroll
                for (int ntp = 0; ntp < 2; ntp++) {
                    uint32_t off = (uint32_t)((wn * 32 + ntp * 16 + b_r) * 128 + kt * 32 + b_kb);
                    off ^= (off >> 3) & 0x70u;
                    ldsm4(b1[ntp], sbase + 3 * TILEB + off);
                }
                #pragma unroll
                for (int mt = 0; mt < 4; mt++)
                    #pragma unroll
                    for (int nt = 0; nt < 4; nt++)
                        mma_fp16(acc[mt][nt], a0[mt], &b1[nt >> 1][(nt & 1) * 2]);
            }
            if (NPASS == 3) {
                uint32_t a1[4][4];
                #pragma unroll
                for (int mt = 0; mt < 4; mt++) {
                    uint32_t off = (uint32_t)((wm * 64 + mt * 16 + a_r) * 128 + kt * 32 + a_kb);
                    off ^= (off >> 3) & 0x70u;
                    ldsm4(a1[mt], sbase + 1 * TILEB + off);
                }
                #pragma unroll
                for (int mt = 0; mt < 4; mt++)
                    #pragma unroll
                    for (int nt = 0; nt < 4; nt++)
                        mma_fp16(acc[mt][nt], a1[mt], &b0[nt >> 1][(nt & 1) * 2]);
            }
        }
        __syncthreads();
    }

    // ---- epilogue ----
    const int qr = lane >> 2;
    const int qc = (lane & 3) * 2;
    #pragma unroll
    for (int mt = 0; mt < 4; mt++) {
        #pragma unroll
        for (int nt = 0; nt < 4; nt++) {
            const long long row0 = m0 + wm * 64 + mt * 16 + qr;
            const long long row1 = row0 + 8;
            const int col = n0 + wn * 32 + nt * 8 + qc;
            float v00 = acc[mt][nt][0], v01 = acc[mt][nt][1];
            float v10 = acc[mt][nt][2], v11 = acc[mt][nt][3];
            if (EPI == 0) {
                *reinterpret_cast<float2*>(Cf + z * sC + row0 * ldc + col) = make_float2(v00, v01);
                *reinterpret_cast<float2*>(Cf + z * sC + row1 * ldc + col) = make_float2(v10, v11);
            } else if (EPI == 1) {
                float b0s = bias[col], b1s = bias[col + 1];
                *reinterpret_cast<float2*>(Cf + z * sC + row0 * ldc + col) =
                    make_float2(tanhf(v00 + b0s), tanhf(v01 + b1s));
                *reinterpret_cast<float2*>(Cf + z * sC + row1 * ldc + col) =
                    make_float2(tanhf(v10 + b0s), tanhf(v11 + b1s));
            } else if (EPI == 2) {
                __half h0, l0, h1, l1;
                split2h(v00, h0, l0); split2h(v01, h1, l1);
                *reinterpret_cast<__half2*>(Cs + z * sC + row0 * ldc + col) = __halves2half2(h0, h1);
                *reinterpret_cast<__half2*>(Cs + z * sC + row0 * ldc + splitOff + col) = __halves2half2(l0, l1);
                split2h(v10, h0, l0); split2h(v11, h1, l1);
                *reinterpret_cast<__half2*>(Cs + z * sC + row1 * ldc + col) = __halves2half2(h0, h1);
                *reinterpret_cast<__half2*>(Cs + z * sC + row1 * ldc + splitOff + col) = __halves2half2(l0, l1);
            } else {   // EPI == 3: hi-only half store
                *reinterpret_cast<__half2*>(Cs + z * sC + row0 * ldc + col) =
                    __halves2half2(__float2half_rn(v00), __float2half_rn(v01));
                *reinterpret_cast<__half2*>(Cs + z * sC + row1 * ldc + col) =
                    __halves2half2(__float2half_rn(v10), __float2half_rn(v11));
            }
        }
    }
}

// ============================================================================
// Conversion kernels (fp16 2-way)
// ============================================================================
__global__ void __launch_bounds__(256) split2_kernel(
    const float* __restrict__ src, __half* __restrict__ dst, int K)
{
    long long i = (long long)blockIdx.x * blockDim.x + threadIdx.x;
    long long rr = i / K;
    int k = (int)(i - rr * K);
    __half h, l;
    split2h(src[i], h, l);
    __half* row = dst + rr * (2LL * K);
    row[k] = h; row[K + k] = l;
}

// dec -> cat2 [8192,4096]: hi at 1024+o, lo at 3072+o (lo needed by GEMM1 pass 3)
__global__ void __launch_bounds__(256) dec_to_cat_kernel(
    const float* __restrict__ dec, __half* __restrict__ cat)
{
    long long i = (long long)blockIdx.x * blockDim.x + threadIdx.x;  // 8192*1024
    long long m = i >> 10;
    int o = (int)(i & 1023);
    __half h, l;
    split2h(dec[i], h, l);
    cat[m * 4096 + 1024 + o] = h;
    cat[m * 4096 + 3072 + o] = l;
}

// enc -> enc2 [b][s, 2048] and encT2 [b][i, 2048] (transposed), h|l
__global__ void __launch_bounds__(1024) enc_split_kernel(
    const float* __restrict__ enc, __half* __restrict__ e2, __half* __restrict__ eT2)
{
    __shared__ __half sh[32][33], sl[32][33];
    int b = blockIdx.z;
    int i0 = blockIdx.x * 32, s0 = blockIdx.y * 32;
    int tx = threadIdx.x, ty = threadIdx.y;
    const float* eb = enc + (size_t)b * S_ * I_;
    float x = eb[(size_t)(s0 + ty) * I_ + i0 + tx];
    __half h, l;
    split2h(x, h, l);
    __half* e2b = e2 + (size_t)b * S_ * 2 * I_;
    e2b[(size_t)(s0 + ty) * 2048 + i0 + tx] = h;
    e2b[(size_t)(s0 + ty) * 2048 + 1024 + i0 + tx] = l;
    sh[ty][tx] = h; sl[ty][tx] = l;
    __syncthreads();
    __half* eTb = eT2 + (size_t)b * I_ * 2 * S_;
    eTb[(size_t)(i0 + ty) * 2048 + s0 + tx] = sh[tx][ty];
    eTb[(size_t)(i0 + ty) * 2048 + 1024 + s0 + tx] = sl[tx][ty];
}

// ============================================================================
// Masked softmax over rows of [B*T, S=1024], in place (fp32); writes hi-split
// only (w_l is never consumed by GEMM4's pass set).
// ============================================================================
__device__ __forceinline__ float warpMax(float v) {
    #pragma unroll
    for (int o = 16; o; o >>= 1) v = fmaxf(v, __shfl_xor_sync(0xffffffffu, v, o));
    return v;
}
__device__ __forceinline__ float warpSum(float v) {
    #pragma unroll
    for (int o = 16; o; o >>= 1) v += __shfl_xor_sync(0xffffffffu, v, o);
    return v;
}

__global__ void __launch_bounds__(256) softmax_mask(
    float* __restrict__ w, const int* __restrict__ mask, __half* __restrict__ wsplit)
{
    const int S = 1024;
    long long row = blockIdx.x;
    int b = (int)(row >> 7);
    float* sr = w + row * S;
    const int* mr = mask + (long long)b * S;
    int tid = threadIdx.x;

    float4 v = *reinterpret_cast<const float4*>(sr + tid * 4);
    int4 m = *reinterpret_cast<const int4*>(mr + tid * 4);

    bool msk[4] = {m.x != 0, m.y != 0, m.z != 0, m.w != 0};
    float x[4];
    x[0] = msk[0] ? -INFINITY : v.x;
    x[1] = msk[1] ? -INFINITY : v.y;
    x[2] = msk[2] ? -INFINITY : v.z;
    x[3] = msk[3] ? -INFINITY : v.w;

    float mx = fmaxf(fmaxf(x[0], x[1]), fmaxf(x[2], x[3]));

    __shared__ float sh[8];
    float wm = warpMax(mx);
    if ((tid & 31) == 0) sh[tid >> 5] = wm;
    __syncthreads();
    if (tid < 32) {
        float t = (tid < 8) ? sh[tid] : -INFINITY;
        t = warpMax(t);
        if (tid == 0) sh[0] = t;
    }
    __syncthreads();
    mx = sh[0];

    float e[4], s = 0.f;
    #pragma unroll
    for (int j = 0; j < 4; j++) {
        e[j] = msk[j] ? 0.f : __expf(x[j] - mx);
        s += e[j];
    }
    __syncthreads();
    float ws = warpSum(s);
    if ((tid & 31) == 0) sh[tid >> 5] = ws;
    __syncthreads();
    if (tid < 32) {
        float t = (tid < 8) ? sh[tid] : 0.f;
        t = warpSum(t);
        if (tid == 0) sh[0] = t;
    }
    __syncthreads();
    float inv = 1.0f / sh[0];

    float o[4] = {e[0] * inv, e[1] * inv, e[2] * inv, e[3] * inv};
    float4 of = {o[0], o[1], o[2], o[3]};
    *reinterpret_cast<float4*>(sr + tid * 4) = of;

    __half* wrow = wsplit + row * 2048;
    __half2 h01 = __halves2half2(__float2half_rn(o[0]), __float2half_rn(o[1]));
    __half2 h23 = __halves2half2(__float2half_rn(o[2]), __float2half_rn(o[3]));
    *reinterpret_cast<__half2*>(wrow + tid * 4 + 0) = h01;
    *reinterpret_cast<__half2*>(wrow + tid * 4 + 2) = h23;
}

// ============================================================================
extern "C" void kernel_launch(void* const* d_in, const int* in_sizes, int n_in,
                              void* d_out, int out_size)
{
    const float* dec    = (const float*)d_in[0];   // [64,128,1024]
    const float* enc    = (const float*)d_in[1];   // [64,1024,1024]
    const int*   mask   = (const int*)d_in[2];     // [64,1024] bool->int32
    const float* W_attn = (const float*)d_in[3];   // [1024,1024]
    const float* W_out  = (const float*)d_in[4];   // [1024,2048]
    const float* b_out  = (const float*)d_in[5];   // [1024]

    float* out     = (float*)d_out;                 // attn_outputs [64,128,1024]
    float* weights = out + (long long)M_ * O_;      // attn_weights [64,128,1024]

    __half *wa2, *qp2, *enc2, *encT2, *w2, *cat2, *wo2;
    cudaGetSymbolAddress((void**)&wa2,   g_wa2);
    cudaGetSymbolAddress((void**)&qp2,   g_qp2);
    cudaGetSymbolAddress((void**)&enc2,  g_enc2);
    cudaGetSymbolAddress((void**)&encT2, g_encT2);
    cudaGetSymbolAddress((void**)&w2,    g_w2);
    cudaGetSymbolAddress((void**)&cat2,  g_cat2);
    cudaGetSymbolAddress((void**)&wo2,   g_wo2);

    const int SMB = 2 * STAGEB;  // 131072 — identical to champion
    cudaFuncSetAttribute((const void*)tgemm<2,3,2>, cudaFuncAttributeMaxDynamicSharedMemorySize, SMB);
    cudaFuncSetAttribute((const void*)tgemm<2,3,0>, cudaFuncAttributeMaxDynamicSharedMemorySize, SMB);
    cudaFuncSetAttribute((const void*)tgemm<1,2,3>, cudaFuncAttributeMaxDynamicSharedMemorySize, SMB);
    cudaFuncSetAttribute((const void*)tgemm<1,2,1>, cudaFuncAttributeMaxDynamicSharedMemorySize, SMB);

    // --- Conversions ---
    split2_kernel<<<(I_ * (long long)O_) / 256, 256>>>(W_attn, wa2, O_);
    split2_kernel<<<(O_ * (long long)C_) / 256, 256>>>(W_out, wo2, C_);
    enc_split_kernel<<<dim3(I_ / 32, S_ / 32, B_), dim3(32, 32)>>>(enc, enc2, encT2);
    dec_to_cat_kernel<<<(M_ * (long long)O_) / 256, 256>>>(dec, cat2);

    // --- GEMM1: q_proj = dec . W_attn^T  (3 passes; A = dec slabs inside cat2) ---
    tgemm<2,3,2><<<dim3(I_ / 128, M_ / 128, 1), 256, SMB>>>(
        cat2 + 1024, wa2, nullptr, qp2, nullptr,
        O_, /*pitchA*/4096, /*pitchB*/2048, /*slabA*/2048, /*slabB*/1024,
        0, 0, 0, 2 * I_, I_);

    // --- GEMM2: scores[b] = q[b] . enc[b]^T  (3 passes) -> weights fp32 ---
    tgemm<2,3,0><<<dim3(S_ / 128, T_ / 128, B_), 256, SMB>>>(
        qp2, enc2, weights, nullptr, nullptr,
        I_, 2 * I_, 2 * I_, I_, I_,
        (long long)T_ * 2 * I_, (long long)S_ * 2 * I_, (long long)T_ * S_,
        S_, 0);

    // --- Softmax + fused hi-only fp16 split -> w2 ---
    softmax_mask<<<M_, 256>>>(weights, mask, w2);

    // --- GEMM4: ctx[b] = w_h[b] . encT[b]^T  (2 passes, A slab1 not fetched,
    //     hi-only store: ctx_l is never consumed) ---
    tgemm<1,2,3><<<dim3(I_ / 128, T_ / 128, B_), 256, SMB>>>(
        w2, encT2, nullptr, cat2, nullptr,
        S_, 2 * S_, 2 * S_, S_, S_,
        (long long)T_ * 2 * S_, (long long)I_ * 2 * S_, (long long)T_ * 2 * C_,
        2 * C_, C_);

    // --- GEMM5: out = tanh(cat_h . W^T + b)  (2 passes: hh + h*W_l; cat_l unused) ---
    tgemm<1,2,1><<<dim3(O_ / 128, M_ / 128, 1), 256, SMB>>>(
        cat2, wo2, out, nullptr, b_out,
        C_, 2 * C_, 2 * C_, C_, C_,
        0, 0, 0, O_, 0);
}

// round 17
// speedup vs baseline: 1.5842x; 1.0695x over previous
#include <cuda_runtime.h>
#include <cuda_fp16.h>
#include <math.h>
#include <stdint.h>

// ============================================================================
// Problem dims
// ============================================================================
#define B_ 64
#define T_ 128
#define S_ 1024
#define I_ 1024
#define O_ 1024
#define M_ (B_*T_)   // 8192
#define C_ (I_+O_)   // 2048

// ============================================================================
// Scratch (__device__ globals). fp16 2-way splits (h|l slabs).
// ============================================================================
__device__ __half g_wa2[I_ * 2 * O_];                    // [1024, 2048]
__device__ __half g_qp2[M_ * 2 * I_];                    // [8192, 2048]
__device__ __half g_enc2[(size_t)B_ * S_ * 2 * I_];      // [64][1024, 2048]
__device__ __half g_encT2[(size_t)B_ * I_ * 2 * S_];     // [64][1024, 2048]; only hi slab written
__device__ __half g_w2[M_ * 2 * S_];                     // [8192, 2048] (only hi slab used)
__device__ __half g_cat2[(size_t)M_ * 2 * C_];           // [8192, 4096] row=[ctx_h|dec_h|ctx_l|dec_l]
__device__ __half g_wo2[O_ * 2 * C_];                    // [1024, 4096]

// ============================================================================
// Helpers
// ============================================================================
__device__ __forceinline__ uint32_t smem_u32(const void* p) {
    uint32_t a;
    asm("{ .reg .u64 t; cvta.to.shared.u64 t, %1; cvt.u32.u64 %0, t; }" : "=r"(a) : "l"(p));
    return a;
}

__device__ __forceinline__ void ldsm4(uint32_t r[4], uint32_t addr) {
    asm volatile("ldmatrix.sync.aligned.m8n8.x4.shared.b16 {%0,%1,%2,%3}, [%4];"
        : "=r"(r[0]), "=r"(r[1]), "=r"(r[2]), "=r"(r[3]) : "r"(addr));
}

__device__ __forceinline__ void mma_fp16(float d[4], const uint32_t a[4], const uint32_t b[2]) {
    asm volatile(
        "mma.sync.aligned.m16n8k16.row.col.f32.f16.f16.f32 "
        "{%0,%1,%2,%3}, {%4,%5,%6,%7}, {%8,%9}, {%0,%1,%2,%3};"
        : "+f"(d[0]), "+f"(d[1]), "+f"(d[2]), "+f"(d[3])
        : "r"(a[0]), "r"(a[1]), "r"(a[2]), "r"(a[3]), "r"(b[0]), "r"(b[1]));
}

__device__ __forceinline__ void split2h(float x, __half& h, __half& l) {
    h = __float2half_rn(x);
    l = __float2half_rn(x - __half2float(h));
}

#define CP_ASYNC16(dst, src) \
    asm volatile("cp.async.cg.shared.global [%0], [%1], 16;" :: "r"(dst), "l"(src))
#define CP_COMMIT() asm volatile("cp.async.commit_group;" ::: "memory")
#define CP_WAIT1()  asm volatile("cp.async.wait_group 1;" ::: "memory")
#define CP_WAIT0()  asm volatile("cp.async.wait_group 0;" ::: "memory")

// ============================================================================
// HMMA GEMM, fp16 2-way split, NT, K-major. R12-identical pipeline skeleton
// (BK=64, 2-stage cp.async, 131KB smem reserved, 256 threads 8 warps 2x4, SW128).
// NAL/NBL = A/B slabs actually FETCHED (layout always reserves 2 each).
// NPASS compute passes with fragment reuse:
//   order: A0xB0, A0xB1 (needs NBL=2), A1xB0 (needs NAL=2)
// EPI: 0 = fp32, 1 = tanh(acc+bias) fp32, 2 = split2h hi+lo, 3 = hi-only half
// ============================================================================
#define TILEB 16384                     // 128x64 half tile bytes
#define STAGEB (4*TILEB)                // layout: [A0][A1][B0][B1] = 65536

template<int NAL, int NBL, int NPASS, int EPI>
__global__ void __launch_bounds__(256) tgemm(
    const __half* __restrict__ A, const __half* __restrict__ B,
    float* __restrict__ Cf, __half* __restrict__ Cs,
    const float* __restrict__ bias,
    int K, int pitchA, int pitchB, int slabA, int slabB,
    long long sA, long long sB, long long sC,
    int ldc, int splitOff)
{
    extern __shared__ char smem[];
    const uint32_t sb = smem_u32(smem);
    const int tid = threadIdx.x;
    const int lane = tid & 31, wid = tid >> 5;
    const int wm = wid & 1, wn = wid >> 1;         // warp tile (wm*64, wn*32)
    const int n0 = blockIdx.x * 128, m0 = blockIdx.y * 128;
    const long long z = blockIdx.z;

    const __half* Ab = A + z * sA;
    const __half* Bb = B + z * sB;

    const int nchunk = K >> 6;

    float acc[4][4][4];
    #pragma unroll
    for (int i = 0; i < 4; i++)
        #pragma unroll
        for (int j = 0; j < 4; j++)
            #pragma unroll
            for (int q = 0; q < 4; q++) acc[i][j][q] = 0.f;

    // ldmatrix lane-address components
    const int g = lane >> 3, lr = lane & 7;
    const int a_r  = lr + (g & 1) * 8;
    const int a_kb = (g >> 1) * 16;
    const int b_r  = lr + (g >> 1) * 8;
    const int b_kb = (g & 1) * 16;

    auto prefetch = [&](int c, int stage) {
        const int k0 = c << 6;
        const uint32_t sbase = sb + stage * STAGEB;
        #pragma unroll
        for (int s = 0; s < NAL; s++) {
            #pragma unroll
            for (int j = 0; j < 4; j++) {       // A slab: 128x64
                int v = tid + 256 * j;
                int r = v >> 3, cc = (v & 7) << 3;
                uint32_t off = (uint32_t)(r * 128 + cc * 2);
                off ^= (off >> 3) & 0x70u;
                CP_ASYNC16(sbase + s * TILEB + off,
                           Ab + (long long)(m0 + r) * pitchA + s * slabA + k0 + cc);
            }
        }
        #pragma unroll
        for (int s = 0; s < NBL; s++) {
            #pragma unroll
            for (int j = 0; j < 4; j++) {       // B slab: 128x64
                int v = tid + 256 * j;
                int r = v >> 3, cc = (v & 7) << 3;
                uint32_t off = (uint32_t)(r * 128 + cc * 2);
                off ^= (off >> 3) & 0x70u;
                CP_ASYNC16(sbase + (2 + s) * TILEB + off,
                           Bb + (long long)(n0 + r) * pitchB + s * slabB + k0 + cc);
            }
        }
    };

    prefetch(0, 0);
    CP_COMMIT();

    for (int c = 0; c < nchunk; c++) {
        const int stage = c & 1;
        if (c + 1 < nchunk) {
            prefetch(c + 1, stage ^ 1);
            CP_COMMIT();
            CP_WAIT1();
        } else {
            CP_WAIT0();
        }
        __syncthreads();

        const uint32_t sbase = sb + stage * STAGEB;
        #pragma unroll
        for (int kt = 0; kt < 4; kt++) {
            uint32_t a0[4][4], b0[2][4];
            #pragma unroll
            for (int mt = 0; mt < 4; mt++) {
                uint32_t off = (uint32_t)((wm * 64 + mt * 16 + a_r) * 128 + kt * 32 + a_kb);
                off ^= (off >> 3) & 0x70u;
                ldsm4(a0[mt], sbase + 0 * TILEB + off);
            }
            #pragma unroll
            for (int ntp = 0; ntp < 2; ntp++) {
                uint32_t off = (uint32_t)((wn * 32 + ntp * 16 + b_r) * 128 + kt * 32 + b_kb);
                off ^= (off >> 3) & 0x70u;
                ldsm4(b0[ntp], sbase + 2 * TILEB + off);
            }
            #pragma unroll
            for (int mt = 0; mt < 4; mt++)
                #pragma unroll
                for (int nt = 0; nt < 4; nt++)
                    mma_fp16(acc[mt][nt], a0[mt], &b0[nt >> 1][(nt & 1) * 2]);

            if (NPASS >= 2) {
                uint32_t b1[2][4];
                #pragma unroll
                for (int ntp = 0; ntp < 2; ntp++) {
                    uint32_t off = (uint32_t)((wn * 32 + ntp * 16 + b_r) * 128 + kt * 32 + b_kb);
                    off ^= (off >> 3) & 0x70u;
                    ldsm4(b1[ntp], sbase + 3 * TILEB + off);
                }
                #pragma unroll
                for (int mt = 0; mt < 4; mt++)
                    #pragma unroll
                    for (int nt = 0; nt < 4; nt++)
                        mma_fp16(acc[mt][nt], a0[mt], &b1[nt >> 1][(nt & 1) * 2]);
            }
            if (NPASS == 3) {
                uint32_t a1[4][4];
                #pragma unroll
                for (int mt = 0; mt < 4; mt++) {
                    uint32_t off = (uint32_t)((wm * 64 + mt * 16 + a_r) * 128 + kt * 32 + a_kb);
                    off ^= (off >> 3) & 0x70u;
                    ldsm4(a1[mt], sbase + 1 * TILEB + off);
                }
                #pragma unroll
                for (int mt = 0; mt < 4; mt++)
                    #pragma unroll
                    for (int nt = 0; nt < 4; nt++)
                        mma_fp16(acc[mt][nt], a1[mt], &b0[nt >> 1][(nt & 1) * 2]);
            }
        }
        __syncthreads();
    }

    // ---- epilogue ----
    const int qr = lane >> 2;
    const int qc = (lane & 3) * 2;
    #pragma unroll
    for (int mt = 0; mt < 4; mt++) {
        #pragma unroll
        for (int nt = 0; nt < 4; nt++) {
            const long long row0 = m0 + wm * 64 + mt * 16 + qr;
            const long long row1 = row0 + 8;
            const int col = n0 + wn * 32 + nt * 8 + qc;
            float v00 = acc[mt][nt][0], v01 = acc[mt][nt][1];
            float v10 = acc[mt][nt][2], v11 = acc[mt][nt][3];
            if (EPI == 0) {
                *reinterpret_cast<float2*>(Cf + z * sC + row0 * ldc + col) = make_float2(v00, v01);
                *reinterpret_cast<float2*>(Cf + z * sC + row1 * ldc + col) = make_float2(v10, v11);
            } else if (EPI == 1) {
                float b0s = bias[col], b1s = bias[col + 1];
                *reinterpret_cast<float2*>(Cf + z * sC + row0 * ldc + col) =
                    make_float2(tanhf(v00 + b0s), tanhf(v01 + b1s));
                *reinterpret_cast<float2*>(Cf + z * sC + row1 * ldc + col) =
                    make_float2(tanhf(v10 + b0s), tanhf(v11 + b1s));
            } else if (EPI == 2) {
                __half h0, l0, h1, l1;
                split2h(v00, h0, l0); split2h(v01, h1, l1);
                *reinterpret_cast<__half2*>(Cs + z * sC + row0 * ldc + col) = __halves2half2(h0, h1);
                *reinterpret_cast<__half2*>(Cs + z * sC + row0 * ldc + splitOff + col) = __halves2half2(l0, l1);
                split2h(v10, h0, l0); split2h(v11, h1, l1);
                *reinterpret_cast<__half2*>(Cs + z * sC + row1 * ldc + col) = __halves2half2(h0, h1);
                *reinterpret_cast<__half2*>(Cs + z * sC + row1 * ldc + splitOff + col) = __halves2half2(l0, l1);
            } else {   // EPI == 3: hi-only half store
                *reinterpret_cast<__half2*>(Cs + z * sC + row0 * ldc + col) =
                    __halves2half2(__float2half_rn(v00), __float2half_rn(v01));
                *reinterpret_cast<__half2*>(Cs + z * sC + row1 * ldc + col) =
                    __halves2half2(__float2half_rn(v10), __float2half_rn(v11));
            }
        }
    }
}

// ============================================================================
// Conversion kernels (fp16 2-way)
// ============================================================================
__global__ void __launch_bounds__(256) split2_kernel(
    const float* __restrict__ src, __half* __restrict__ dst, int K)
{
    long long i = (long long)blockIdx.x * blockDim.x + threadIdx.x;
    long long rr = i / K;
    int k = (int)(i - rr * K);
    __half h, l;
    split2h(src[i], h, l);
    __half* row = dst + rr * (2LL * K);
    row[k] = h; row[K + k] = l;
}

// dec -> cat2 [8192,4096]: hi at 1024+o, lo at 3072+o (lo needed by GEMM1 pass 3)
__global__ void __launch_bounds__(256) dec_to_cat_kernel(
    const float* __restrict__ dec, __half* __restrict__ cat)
{
    long long i = (long long)blockIdx.x * blockDim.x + threadIdx.x;  // 8192*1024
    long long m = i >> 10;
    int o = (int)(i & 1023);
    __half h, l;
    split2h(dec[i], h, l);
    cat[m * 4096 + 1024 + o] = h;
    cat[m * 4096 + 3072 + o] = l;
}

// enc -> enc2 [b][s, 2048] (h|l) and encT2 [b][i, 0:1024] (transposed, HI ONLY —
// the lo transposed slab is dead: GEMM4 runs a single hh pass).
__global__ void __launch_bounds__(1024) enc_split_kernel(
    const float* __restrict__ enc, __half* __restrict__ e2, __half* __restrict__ eT2)
{
    __shared__ __half sh[32][33];
    int b = blockIdx.z;
    int i0 = blockIdx.x * 32, s0 = blockIdx.y * 32;
    int tx = threadIdx.x, ty = threadIdx.y;
    const float* eb = enc + (size_t)b * S_ * I_;
    float x = eb[(size_t)(s0 + ty) * I_ + i0 + tx];
    __half h, l;
    split2h(x, h, l);
    __half* e2b = e2 + (size_t)b * S_ * 2 * I_;
    e2b[(size_t)(s0 + ty) * 2048 + i0 + tx] = h;
    e2b[(size_t)(s0 + ty) * 2048 + 1024 + i0 + tx] = l;
    sh[ty][tx] = h;
    __syncthreads();
    __half* eTb = eT2 + (size_t)b * I_ * 2 * S_;
    eTb[(size_t)(i0 + ty) * 2048 + s0 + tx] = sh[tx][ty];
}

// ============================================================================
// Masked softmax over rows of [B*T, S=1024], in place (fp32); writes hi-split
// only (w_l is never consumed).
// ============================================================================
__device__ __forceinline__ float warpMax(float v) {
    #pragma unroll
    for (int o = 16; o; o >>= 1) v = fmaxf(v, __shfl_xor_sync(0xffffffffu, v, o));
    return v;
}
__device__ __forceinline__ float warpSum(float v) {
    #pragma unroll
    for (int o = 16; o; o >>= 1) v += __shfl_xor_sync(0xffffffffu, v, o);
    return v;
}

__global__ void __launch_bounds__(256) softmax_mask(
    float* __restrict__ w, const int* __restrict__ mask, __half* __restrict__ wsplit)
{
    const int S = 1024;
    long long row = blockIdx.x;
    int b = (int)(row >> 7);
    float* sr = w + row * S;
    const int* mr = mask + (long long)b * S;
    int tid = threadIdx.x;

    float4 v = *reinterpret_cast<const float4*>(sr + tid * 4);
    int4 m = *reinterpret_cast<const int4*>(mr + tid * 4);

    bool msk[4] = {m.x != 0, m.y != 0, m.z != 0, m.w != 0};
    float x[4];
    x[0] = msk[0] ? -INFINITY : v.x;
    x[1] = msk[1] ? -INFINITY : v.y;
    x[2] = msk[2] ? -INFINITY : v.z;
    x[3] = msk[3] ? -INFINITY : v.w;

    float mx = fmaxf(fmaxf(x[0], x[1]), fmaxf(x[2], x[3]));

    __shared__ float sh[8];
    float wm = warpMax(mx);
    if ((tid & 31) == 0) sh[tid >> 5] = wm;
    __syncthreads();
    if (tid < 32) {
        float t = (tid < 8) ? sh[tid] : -INFINITY;
        t = warpMax(t);
        if (tid == 0) sh[0] = t;
    }
    __syncthreads();
    mx = sh[0];

    float e[4], s = 0.f;
    #pragma unroll
    for (int j = 0; j < 4; j++) {
        e[j] = msk[j] ? 0.f : __expf(x[j] - mx);
        s += e[j];
    }
    __syncthreads();
    float ws = warpSum(s);
    if ((tid & 31) == 0) sh[tid >> 5] = ws;
    __syncthreads();
    if (tid < 32) {
        float t = (tid < 8) ? sh[tid] : 0.f;
        t = warpSum(t);
        if (tid == 0) sh[0] = t;
    }
    __syncthreads();
    float inv = 1.0f / sh[0];

    float o[4] = {e[0] * inv, e[1] * inv, e[2] * inv, e[3] * inv};
    float4 of = {o[0], o[1], o[2], o[3]};
    *reinterpret_cast<float4*>(sr + tid * 4) = of;

    __half* wrow = wsplit + row * 2048;
    __half2 h01 = __halves2half2(__float2half_rn(o[0]), __float2half_rn(o[1]));
    __half2 h23 = __halves2half2(__float2half_rn(o[2]), __float2half_rn(o[3]));
    *reinterpret_cast<__half2*>(wrow + tid * 4 + 0) = h01;
    *reinterpret_cast<__half2*>(wrow + tid * 4 + 2) = h23;
}

// ============================================================================
extern "C" void kernel_launch(void* const* d_in, const int* in_sizes, int n_in,
                              void* d_out, int out_size)
{
    const float* dec    = (const float*)d_in[0];   // [64,128,1024]
    const float* enc    = (const float*)d_in[1];   // [64,1024,1024]
    const int*   mask   = (const int*)d_in[2];     // [64,1024] bool->int32
    const float* W_attn = (const float*)d_in[3];   // [1024,1024]
    const float* W_out  = (const float*)d_in[4];   // [1024,2048]
    const float* b_out  = (const float*)d_in[5];   // [1024]

    float* out     = (float*)d_out;                 // attn_outputs [64,128,1024]
    float* weights = out + (long long)M_ * O_;      // attn_weights [64,128,1024]

    __half *wa2, *qp2, *enc2, *encT2, *w2, *cat2, *wo2;
    cudaGetSymbolAddress((void**)&wa2,   g_wa2);
    cudaGetSymbolAddress((void**)&qp2,   g_qp2);
    cudaGetSymbolAddress((void**)&enc2,  g_enc2);
    cudaGetSymbolAddress((void**)&encT2, g_encT2);
    cudaGetSymbolAddress((void**)&w2,    g_w2);
    cudaGetSymbolAddress((void**)&cat2,  g_cat2);
    cudaGetSymbolAddress((void**)&wo2,   g_wo2);

    const int SMB = 2 * STAGEB;  // 131072 — identical to champion
    cudaFuncSetAttribute((const void*)tgemm<2,2,3,2>, cudaFuncAttributeMaxDynamicSharedMemorySize, SMB);
    cudaFuncSetAttribute((const void*)tgemm<2,2,3,0>, cudaFuncAttributeMaxDynamicSharedMemorySize, SMB);
    cudaFuncSetAttribute((const void*)tgemm<1,1,1,3>, cudaFuncAttributeMaxDynamicSharedMemorySize, SMB);
    cudaFuncSetAttribute((const void*)tgemm<1,2,2,1>, cudaFuncAttributeMaxDynamicSharedMemorySize, SMB);

    // --- Conversions ---
    split2_kernel<<<(I_ * (long long)O_) / 256, 256>>>(W_attn, wa2, O_);
    split2_kernel<<<(O_ * (long long)C_) / 256, 256>>>(W_out, wo2, C_);
    enc_split_kernel<<<dim3(I_ / 32, S_ / 32, B_), dim3(32, 32)>>>(enc, enc2, encT2);
    dec_to_cat_kernel<<<(M_ * (long long)O_) / 256, 256>>>(dec, cat2);

    // --- GEMM1: q_proj = dec . W_attn^T  (3 passes; A = dec slabs inside cat2) ---
    tgemm<2,2,3,2><<<dim3(I_ / 128, M_ / 128, 1), 256, SMB>>>(
        cat2 + 1024, wa2, nullptr, qp2, nullptr,
        O_, /*pitchA*/4096, /*pitchB*/2048, /*slabA*/2048, /*slabB*/1024,
        0, 0, 0, 2 * I_, I_);

    // --- GEMM2: scores[b] = q[b] . enc[b]^T  (3 passes) -> weights fp32 ---
    tgemm<2,2,3,0><<<dim3(S_ / 128, T_ / 128, B_), 256, SMB>>>(
        qp2, enc2, weights, nullptr, nullptr,
        I_, 2 * I_, 2 * I_, I_, I_,
        (long long)T_ * 2 * I_, (long long)S_ * 2 * I_, (long long)T_ * S_,
        S_, 0);

    // --- Softmax + fused hi-only fp16 split -> w2 ---
    softmax_mask<<<M_, 256>>>(weights, mask, w2);

    // --- GEMM4: ctx[b] = w_h[b] . encT_h[b]^T  (1 pass hh — R10-validated;
    //     only slab 0 of A and B fetched; hi-only store) ---
    tgemm<1,1,1,3><<<dim3(I_ / 128, T_ / 128, B_), 256, SMB>>>(
        w2, encT2, nullptr, cat2, nullptr,
        S_, 2 * S_, 2 * S_, S_, S_,
        (long long)T_ * 2 * S_, (long long)I_ * 2 * S_, (long long)T_ * 2 * C_,
        2 * C_, C_);

    // --- GEMM5: out = tanh(cat_h . W^T + b)  (2 passes: hh + h*W_l) ---
    tgemm<1,2,2,1><<<dim3(O_ / 128, M_ / 128, 1), 256, SMB>>>(
        cat2, wo2, out, nullptr, b_out,
        C_, 2 * C_, 2 * C_, C_, C_,
        0, 0, 0, O_, 0);
}